// round 9
// baseline (speedup 1.0000x reference)
#include <cuda_runtime.h>

#define EPSV2    1e-8f         // EPSV^2
#define TOLSQ    9e-10f        // (3e-5)^2 relative orthogonality threshold
#define MAXSWEEP 30
#define FULLM    0xffffffffu

// One CTA per 64x64 SPD matrix. One-sided Jacobi, register-resident columns,
// hierarchical tournament (R8), plus R9: CARRIED NORMS. Each team keeps the
// squared norms of its T/B half-block columns as team-uniform registers
// (nrmT/nrmB) that travel with the columns through every exchange. VISIT then
// needs only the cross-dot (8 FMA + 3 shfl); at rotation time the shrinking
// column's norm is recomputed exactly from live registers (butterfly inside
// the branch is safe: condition is team-uniform, mask tm covers the team),
// the growing one is (dpp+dqq)-small. Threshold never sees drift.
__global__ void __launch_bounds__(256, 4)
logm_jacobi_kernel(const float* __restrict__ in, float* __restrict__ out)
{
    __shared__ __align__(16) float SH[8192];   // staging; epilogue U matrix
    __shared__ float stN[2][2][8][4];          // parity x T/B x warp x team norms
    __shared__ float wlog[64];
    __shared__ int   s_flag;

    const int tid  = threadIdx.x;
    const int lane = tid & 31;
    const int warp = tid >> 5;
    const int team = lane >> 3;               // 4 teams per warp
    const int sl   = lane & 7;                // lane within team
    const unsigned tm = 0xffu << (team << 3); // team shfl mask
    const size_t base = (size_t)blockIdx.x * 4096;

    // pair visit with carried norms NT/NB (team-uniform squared norms)
#define VISIT(TT, BB, NT, NB)                                                \
    {                                                                        \
        float dpq = 0.f;                                                     \
        _Pragma("unroll")                                                    \
        for (int i = 0; i < 8; ++i) dpq = fmaf(TT[i], BB[i], dpq);           \
        _Pragma("unroll")                                                    \
        for (int o = 4; o; o >>= 1) dpq += __shfl_xor_sync(tm, dpq, o);      \
        float dpp = NT, dqq = NB;                                            \
        if (dpq * dpq > TOLSQ * dpp * dqq) {                                 \
            float tau = __fdividef(dqq - dpp, 2.0f * dpq);                   \
            float t = copysignf(1.0f, tau) /                                 \
                      (fabsf(tau) + sqrtf(1.0f + tau * tau));                \
            float c = rsqrtf(1.0f + t * t);                                  \
            float s = t * c;                                                 \
            _Pragma("unroll")                                                \
            for (int i = 0; i < 8; ++i) {                                    \
                float tp = c * TT[i] - s * BB[i];                            \
                BB[i]    = s * TT[i] + c * BB[i];                            \
                TT[i]    = tp;                                               \
            }                                                                \
            bool pshr = (dqq >= dpp);     /* the larger grows */             \
            float small = 0.f;                                               \
            _Pragma("unroll")                                                \
            for (int i = 0; i < 8; ++i) {                                    \
                float v = pshr ? TT[i] : BB[i];                              \
                small = fmaf(v, v, small);                                   \
            }                                                                \
            _Pragma("unroll")                                                \
            for (int o = 4; o; o >>= 1)                                      \
                small += __shfl_xor_sync(tm, small, o);                      \
            float big = (dpp + dqq) - small;                                 \
            NT = pshr ? small : big;                                         \
            NB = pshr ? big   : small;                                       \
            if (sl == 0) s_flag = 1;                                         \
        }                                                                    \
    }

    // ---- load: warp w team t holds cols 4w+t (T) and 32+4w+t (B) ----
    float T[8], B[8];
    {
        const int c = warp * 4 + team;
        const float4* gt = reinterpret_cast<const float4*>(in + base + c * 64 + sl * 8);
        const float4* gb = reinterpret_cast<const float4*>(in + base + (32 + c) * 64 + sl * 8);
        float4 t0 = gt[0], t1 = gt[1], b0 = gb[0], b1 = gb[1];
        T[0]=t0.x; T[1]=t0.y; T[2]=t0.z; T[3]=t0.w;
        T[4]=t1.x; T[5]=t1.y; T[6]=t1.z; T[7]=t1.w;
        B[0]=b0.x; B[1]=b0.y; B[2]=b0.z; B[3]=b0.w;
        B[4]=b1.x; B[5]=b1.y; B[6]=b1.z; B[7]=b1.w;
    }

    // ---- initial exact norms (team-uniform after butterfly) ----
    float nrmT = 0.f, nrmB = 0.f;
    #pragma unroll
    for (int i = 0; i < 8; ++i) {
        nrmT = fmaf(T[i], T[i], nrmT);
        nrmB = fmaf(B[i], B[i], nrmB);
    }
    #pragma unroll
    for (int o = 4; o; o >>= 1) {
        nrmT += __shfl_xor_sync(tm, nrmT, o);
        nrmB += __shfl_xor_sync(tm, nrmB, o);
    }

    const int rotsrc = (lane + 8) & 31;       // +1-team rotation source

    for (int sweep = 0; sweep < MAXSWEEP; ++sweep) {
        if (tid == 0) s_flag = 0;
        __syncthreads();

        for (int outer = 0; outer < 15; ++outer) {
            // ---- 4 inner cross rounds (intra-warp only) ----
            #pragma unroll
            for (int rho = 0; rho < 4; ++rho) {
                VISIT(T, B, nrmT, nrmB);
                #pragma unroll
                for (int i = 0; i < 8; ++i)      // rotate B one team
                    B[i] = __shfl_sync(FULLM, B[i], rotsrc);
                nrmB = __shfl_sync(FULLM, nrmB, rotsrc);
            }

            // ---- intra-half pairs, once per sweep ----
            if (outer == 0) {
                // gather: t0:(tc0,tc1) t1:(tc2,tc3) t2:(bc0,bc1) t3:(bc2,bc3)
                const int sTA = (team == 1) ? rotsrc : lane;
                const int sBA = (team == 2) ? ((lane + 16) & 31) : ((lane + 24) & 31);
                const int sTB = (team == 0) ? rotsrc : ((lane + 16) & 31);
                const int sBB = (team == 2) ? ((lane + 24) & 31) : lane;
                #pragma unroll
                for (int i = 0; i < 8; ++i) {
                    float tA = __shfl_sync(FULLM, T[i], sTA);
                    float bA = __shfl_sync(FULLM, B[i], sBA);
                    float tB = __shfl_sync(FULLM, T[i], sTB);
                    float bB = __shfl_sync(FULLM, B[i], sBB);
                    T[i] = (team < 2) ? tA : bA;
                    B[i] = (team < 2) ? tB : bB;
                }
                {   // norms follow the identical permutation
                    float a = __shfl_sync(FULLM, nrmT, sTA);
                    float b = __shfl_sync(FULLM, nrmB, sBA);
                    float c = __shfl_sync(FULLM, nrmT, sTB);
                    float d = __shfl_sync(FULLM, nrmB, sBB);
                    nrmT = (team < 2) ? a : b;
                    nrmB = (team < 2) ? c : d;
                }
                VISIT(T, B, nrmT, nrmB);
                {   // swap1: even.B <-> odd.T (xor 8)
                    const bool ev = ((team & 1) == 0);
                    #pragma unroll
                    for (int i = 0; i < 8; ++i) {
                        float tx = __shfl_xor_sync(FULLM, T[i], 8);
                        float bx = __shfl_xor_sync(FULLM, B[i], 8);
                        float nB_ = ev ? tx : B[i];
                        float nT_ = ev ? T[i] : bx;
                        T[i] = nT_; B[i] = nB_;
                    }
                    float ntx = __shfl_xor_sync(FULLM, nrmT, 8);
                    float nbx = __shfl_xor_sync(FULLM, nrmB, 8);
                    float nB_ = ev ? ntx : nrmB;
                    float nT_ = ev ? nrmT : nbx;
                    nrmT = nT_; nrmB = nB_;
                }
                VISIT(T, B, nrmT, nrmB);
                #pragma unroll
                for (int i = 0; i < 8; ++i)      // swap2: B <-> B (xor 8)
                    B[i] = __shfl_xor_sync(FULLM, B[i], 8);
                nrmB = __shfl_xor_sync(FULLM, nrmB, 8);
                VISIT(T, B, nrmT, nrmB);
                // restore home: t:(tc_t, bc_t)
                const int rT = (team == 2) ? ((lane + 24) & 31) : rotsrc;
                const int rB = (team == 2) ? rotsrc : ((lane + 24) & 31);
                const int r16 = (lane + 16) & 31;
                #pragma unroll
                for (int i = 0; i < 8; ++i) {
                    float rb  = __shfl_sync(FULLM, B[i], rT);
                    float rt  = __shfl_sync(FULLM, T[i], r16);
                    float rb2 = __shfl_sync(FULLM, B[i], rB);
                    T[i] = (team < 2) ? T[i] : rb;
                    B[i] = (team < 2) ? rt   : rb2;
                }
                {
                    float nrb  = __shfl_sync(FULLM, nrmB, rT);
                    float nrt  = __shfl_sync(FULLM, nrmT, r16);
                    float nrb2 = __shfl_sync(FULLM, nrmB, rB);
                    nrmT = (team < 2) ? nrmT : nrb;
                    nrmB = (team < 2) ? nrt  : nrb2;
                }
            }

            // ---- outer rotation: half-blocks + norms through the ring ----
            const int par = outer & 1;
            float* st  = SH + par * 4096;
            float* stT = st;                       // [warp][256]
            float* stB = st + 2048;
            const int off = team * 64 + sl * 8;
            if (warp >= 1 && warp <= 6) {          // TH -> warp+1
                float4* d = reinterpret_cast<float4*>(stT + (warp + 1) * 256 + off);
                d[0] = make_float4(T[0], T[1], T[2], T[3]);
                d[1] = make_float4(T[4], T[5], T[6], T[7]);
                if (sl == 0) stN[par][0][warp + 1][team] = nrmT;
            }
            if (warp == 0) {                       // BH_0 -> warp1's TH
                float4* d = reinterpret_cast<float4*>(stT + 1 * 256 + off);
                d[0] = make_float4(B[0], B[1], B[2], B[3]);
                d[1] = make_float4(B[4], B[5], B[6], B[7]);
                if (sl == 0) stN[par][0][1][team] = nrmB;
            }
            if (warp >= 1) {                       // BH -> warp-1
                float4* d = reinterpret_cast<float4*>(stB + (warp - 1) * 256 + off);
                d[0] = make_float4(B[0], B[1], B[2], B[3]);
                d[1] = make_float4(B[4], B[5], B[6], B[7]);
                if (sl == 0) stN[par][1][warp - 1][team] = nrmB;
            }
            if (warp == 7) {                       // TH_7 -> own BH
                #pragma unroll
                for (int i = 0; i < 8; ++i) B[i] = T[i];
                nrmB = nrmT;
            }
            __syncthreads();
            if (warp >= 1) {                       // receive TH
                const float4* s4 = reinterpret_cast<const float4*>(stT + warp * 256 + off);
                float4 a = s4[0], b = s4[1];
                T[0]=a.x; T[1]=a.y; T[2]=a.z; T[3]=a.w;
                T[4]=b.x; T[5]=b.y; T[6]=b.z; T[7]=b.w;
                nrmT = stN[par][0][warp][team];
            }
            if (warp <= 6) {                       // receive BH
                const float4* s4 = reinterpret_cast<const float4*>(stB + warp * 256 + off);
                float4 a = s4[0], b = s4[1];
                B[0]=a.x; B[1]=a.y; B[2]=a.z; B[3]=a.w;
                B[4]=b.x; B[5]=b.y; B[6]=b.z; B[7]=b.w;
                nrmB = stN[par][1][warp][team];
            }
        }

        int active = s_flag;
        __syncthreads();
        if (!active) break;
    }

    // ---- exact norms -> eigenvalues; normalized columns -> SH ----
    {
        const int k = warp * 4 + team;
        float dpp = 0.f, dqq = 0.f;
        #pragma unroll
        for (int i = 0; i < 8; ++i) {
            dpp = fmaf(T[i], T[i], dpp);
            dqq = fmaf(B[i], B[i], dqq);
        }
        #pragma unroll
        for (int o = 4; o; o >>= 1) {
            dpp += __shfl_xor_sync(tm, dpp, o);
            dqq += __shfl_xor_sync(tm, dqq, o);
        }
        float it = (dpp > 1e-30f) ? rsqrtf(dpp) : 0.0f;
        float ib = (dqq > 1e-30f) ? rsqrtf(dqq) : 0.0f;
        float4* mt = reinterpret_cast<float4*>(SH + (2 * k) * 64 + sl * 8);
        float4* mb = reinterpret_cast<float4*>(SH + (2 * k + 1) * 64 + sl * 8);
        mt[0] = make_float4(T[0]*it, T[1]*it, T[2]*it, T[3]*it);
        mt[1] = make_float4(T[4]*it, T[5]*it, T[6]*it, T[7]*it);
        mb[0] = make_float4(B[0]*ib, B[1]*ib, B[2]*ib, B[3]*ib);
        mb[1] = make_float4(B[4]*ib, B[5]*ib, B[6]*ib, B[7]*ib);
        if (sl == 0) {
            wlog[2 * k]     = 0.5f * logf(fmaxf(dpp, EPSV2));
            wlog[2 * k + 1] = 0.5f * logf(fmaxf(dqq, EPSV2));
        }
    }
    __syncthreads();

    // ---- O = U diag(w) U^T, 4x4 register tile per thread ----
    const int ta = tid >> 4;
    const int tb = tid & 15;
    float acc[4][4];
    #pragma unroll
    for (int i = 0; i < 4; ++i)
        #pragma unroll
        for (int j = 0; j < 4; ++j) acc[i][j] = 0.0f;

    for (int kk = 0; kk < 64; ++kk) {
        float w = wlog[kk];
        float4 ur = *reinterpret_cast<const float4*>(SH + kk * 64 + 4 * ta);
        float4 uc = *reinterpret_cast<const float4*>(SH + kk * 64 + 4 * tb);
        float r0 = w * ur.x, r1 = w * ur.y, r2 = w * ur.z, r3 = w * ur.w;
        acc[0][0] += r0 * uc.x; acc[0][1] += r0 * uc.y; acc[0][2] += r0 * uc.z; acc[0][3] += r0 * uc.w;
        acc[1][0] += r1 * uc.x; acc[1][1] += r1 * uc.y; acc[1][2] += r1 * uc.z; acc[1][3] += r1 * uc.w;
        acc[2][0] += r2 * uc.x; acc[2][1] += r2 * uc.y; acc[2][2] += r2 * uc.z; acc[2][3] += r2 * uc.w;
        acc[3][0] += r3 * uc.x; acc[3][1] += r3 * uc.y; acc[3][2] += r3 * uc.z; acc[3][3] += r3 * uc.w;
    }

    float* go = out + base;
    #pragma unroll
    for (int i = 0; i < 4; ++i) {
        float4 v = make_float4(acc[i][0], acc[i][1], acc[i][2], acc[i][3]);
        *reinterpret_cast<float4*>(go + (4 * ta + i) * 64 + 4 * tb) = v;
    }
#undef VISIT
}

extern "C" void kernel_launch(void* const* d_in, const int* in_sizes, int n_in,
                              void* d_out, int out_size)
{
    const float* x = (const float*)d_in[0];
    float* out = (float*)d_out;
    int batches = in_sizes[0] / 4096;
    logm_jacobi_kernel<<<batches, 256>>>(x, out);
}

// round 10
// speedup vs baseline: 1.0476x; 1.0476x over previous
#include <cuda_runtime.h>

#define EPSV2    1e-8f         // EPSV^2
#define TOLSQ    9e-10f        // (3e-5)^2 relative orthogonality threshold
#define MAXSWEEP 30
#define FULLM    0xffffffffu

typedef unsigned long long u64;

// ---- packed f32x2 helpers (sm_10x; ptxas never emits these from C++) ----
__device__ __forceinline__ u64 mul2(u64 a, u64 b) {
    u64 r; asm("mul.rn.f32x2 %0, %1, %2;" : "=l"(r) : "l"(a), "l"(b)); return r;
}
__device__ __forceinline__ u64 fma2(u64 a, u64 b, u64 c) {
    u64 r; asm("fma.rn.f32x2 %0, %1, %2, %3;" : "=l"(r) : "l"(a), "l"(b), "l"(c)); return r;
}
__device__ __forceinline__ u64 pack2(float lo, float hi) {
    u64 r; asm("mov.b64 %0, {%1, %2};" : "=l"(r) : "f"(lo), "f"(hi)); return r;
}
__device__ __forceinline__ float hadd2(u64 a) {
    float lo, hi; asm("mov.b64 {%0, %1}, %2;" : "=f"(lo), "=f"(hi) : "l"(a));
    return lo + hi;
}

// One CTA per 64x64 SPD matrix. One-sided Jacobi, register-resident columns,
// hierarchical tournament (R8 structure, which is the validated best), with
// R10: columns held as packed f32x2 (u64[4] per half-column per lane).
// Dots: 12 FMA2 in 3 INDEPENDENT chains of depth 4 (R4/R9 lesson: keep
// parallel chains); rotation math halved to 16 packed ops. Per-lane results
// bit-identical to R8. All shfls unconditional.
__global__ void __launch_bounds__(256, 4)
logm_jacobi_kernel(const float* __restrict__ in, float* __restrict__ out)
{
    __shared__ __align__(16) float SH[8192];   // staging; epilogue U matrix
    __shared__ float wlog[64];
    __shared__ int   s_flag;

    const int tid  = threadIdx.x;
    const int lane = tid & 31;
    const int warp = tid >> 5;
    const int team = lane >> 3;               // 4 teams per warp
    const int sl   = lane & 7;                // lane within team
    const unsigned tm = 0xffu << (team << 3); // team shfl mask
    const size_t base = (size_t)blockIdx.x * 4096;

    // pair visit: 3 packed dots (independent chains) + butterfly + rotation
#define VISIT(TT, BB)                                                        \
    {                                                                        \
        u64 dpq2 = mul2(TT[0], BB[0]);                                       \
        u64 dpp2 = mul2(TT[0], TT[0]);                                       \
        u64 dqq2 = mul2(BB[0], BB[0]);                                       \
        _Pragma("unroll")                                                    \
        for (int i = 1; i < 4; ++i) {                                        \
            dpq2 = fma2(TT[i], BB[i], dpq2);                                 \
            dpp2 = fma2(TT[i], TT[i], dpp2);                                 \
            dqq2 = fma2(BB[i], BB[i], dqq2);                                 \
        }                                                                    \
        float dpq = hadd2(dpq2);                                             \
        float dpp = hadd2(dpp2);                                             \
        float dqq = hadd2(dqq2);                                             \
        _Pragma("unroll")                                                    \
        for (int o = 4; o; o >>= 1) {                                        \
            dpq += __shfl_xor_sync(tm, dpq, o);                              \
            dpp += __shfl_xor_sync(tm, dpp, o);                              \
            dqq += __shfl_xor_sync(tm, dqq, o);                              \
        }                                                                    \
        if (dpq * dpq > TOLSQ * dpp * dqq) {                                 \
            float tau = __fdividef(dqq - dpp, 2.0f * dpq);                   \
            float t = copysignf(1.0f, tau) /                                 \
                      (fabsf(tau) + sqrtf(1.0f + tau * tau));                \
            float c = rsqrtf(1.0f + t * t);                                  \
            float s = t * c;                                                 \
            u64 c2  = pack2(c, c);                                           \
            u64 s2  = pack2(s, s);                                           \
            u64 ms2 = pack2(-s, -s);                                         \
            _Pragma("unroll")                                                \
            for (int i = 0; i < 4; ++i) {                                    \
                u64 tp = fma2(ms2, BB[i], mul2(c2, TT[i]));                  \
                BB[i]  = fma2(s2,  TT[i], mul2(c2, BB[i]));                  \
                TT[i]  = tp;                                                 \
            }                                                                \
            if (sl == 0) s_flag = 1;                                         \
        }                                                                    \
    }

    // ---- load: warp w team t holds cols 4w+t (T) and 32+4w+t (B) ----
    u64 T[4], B[4];
    {
        const int c = warp * 4 + team;
        const ulonglong2* gt = reinterpret_cast<const ulonglong2*>(in + base + c * 64 + sl * 8);
        const ulonglong2* gb = reinterpret_cast<const ulonglong2*>(in + base + (32 + c) * 64 + sl * 8);
        ulonglong2 t0 = gt[0], t1 = gt[1], b0 = gb[0], b1 = gb[1];
        T[0]=t0.x; T[1]=t0.y; T[2]=t1.x; T[3]=t1.y;
        B[0]=b0.x; B[1]=b0.y; B[2]=b1.x; B[3]=b1.y;
    }

    const int rotsrc = (lane + 8) & 31;       // +1-team rotation source

    for (int sweep = 0; sweep < MAXSWEEP; ++sweep) {
        if (tid == 0) s_flag = 0;
        __syncthreads();

        for (int outer = 0; outer < 15; ++outer) {
            // ---- 4 inner cross rounds (intra-warp only) ----
            #pragma unroll
            for (int rho = 0; rho < 4; ++rho) {
                VISIT(T, B);
                #pragma unroll
                for (int i = 0; i < 4; ++i)      // rotate B one team
                    B[i] = __shfl_sync(FULLM, B[i], rotsrc);
            }

            // ---- intra-half pairs, once per sweep ----
            if (outer == 0) {
                // gather: t0:(tc0,tc1) t1:(tc2,tc3) t2:(bc0,bc1) t3:(bc2,bc3)
                const int sTA = (team == 1) ? rotsrc : lane;
                const int sBA = (team == 2) ? ((lane + 16) & 31) : ((lane + 24) & 31);
                const int sTB = (team == 0) ? rotsrc : ((lane + 16) & 31);
                const int sBB = (team == 2) ? ((lane + 24) & 31) : lane;
                #pragma unroll
                for (int i = 0; i < 4; ++i) {
                    u64 tA = __shfl_sync(FULLM, T[i], sTA);
                    u64 bA = __shfl_sync(FULLM, B[i], sBA);
                    u64 tB = __shfl_sync(FULLM, T[i], sTB);
                    u64 bB = __shfl_sync(FULLM, B[i], sBB);
                    T[i] = (team < 2) ? tA : bA;
                    B[i] = (team < 2) ? tB : bB;
                }
                VISIT(T, B);
                {   // swap1: even.B <-> odd.T (xor 8)
                    const bool ev = ((team & 1) == 0);
                    #pragma unroll
                    for (int i = 0; i < 4; ++i) {
                        u64 tx = __shfl_xor_sync(FULLM, T[i], 8);
                        u64 bx = __shfl_xor_sync(FULLM, B[i], 8);
                        u64 nB = ev ? tx : B[i];
                        u64 nT = ev ? T[i] : bx;
                        T[i] = nT; B[i] = nB;
                    }
                }
                VISIT(T, B);
                #pragma unroll
                for (int i = 0; i < 4; ++i)      // swap2: B <-> B (xor 8)
                    B[i] = __shfl_xor_sync(FULLM, B[i], 8);
                VISIT(T, B);
                // restore home: t:(tc_t, bc_t)
                const int rT = (team == 2) ? ((lane + 24) & 31) : rotsrc;
                const int rB = (team == 2) ? rotsrc : ((lane + 24) & 31);
                const int r16 = (lane + 16) & 31;
                #pragma unroll
                for (int i = 0; i < 4; ++i) {
                    u64 rb  = __shfl_sync(FULLM, B[i], rT);
                    u64 rt  = __shfl_sync(FULLM, T[i], r16);
                    u64 rb2 = __shfl_sync(FULLM, B[i], rB);
                    T[i] = (team < 2) ? T[i] : rb;
                    B[i] = (team < 2) ? rt   : rb2;
                }
            }

            // ---- outer rotation: half-blocks through the ring via staging ----
            u64* st  = reinterpret_cast<u64*>(SH) + (outer & 1) * 2048;
            u64* stT = st;                         // [warp][128] u64
            u64* stB = st + 1024;
            const int off = team * 32 + sl * 4;    // u64 units
            if (warp >= 1 && warp <= 6) {          // TH -> warp+1
                ulonglong2* d = reinterpret_cast<ulonglong2*>(stT + (warp + 1) * 128 + off);
                d[0] = make_ulonglong2(T[0], T[1]);
                d[1] = make_ulonglong2(T[2], T[3]);
            }
            if (warp == 0) {                       // BH_0 -> warp1's TH
                ulonglong2* d = reinterpret_cast<ulonglong2*>(stT + 1 * 128 + off);
                d[0] = make_ulonglong2(B[0], B[1]);
                d[1] = make_ulonglong2(B[2], B[3]);
            }
            if (warp >= 1) {                       // BH -> warp-1
                ulonglong2* d = reinterpret_cast<ulonglong2*>(stB + (warp - 1) * 128 + off);
                d[0] = make_ulonglong2(B[0], B[1]);
                d[1] = make_ulonglong2(B[2], B[3]);
            }
            if (warp == 7) {                       // TH_7 -> own BH
                #pragma unroll
                for (int i = 0; i < 4; ++i) B[i] = T[i];
            }
            __syncthreads();
            if (warp >= 1) {                       // receive TH
                const ulonglong2* s4 = reinterpret_cast<const ulonglong2*>(stT + warp * 128 + off);
                ulonglong2 a = s4[0], b = s4[1];
                T[0]=a.x; T[1]=a.y; T[2]=b.x; T[3]=b.y;
            }
            if (warp <= 6) {                       // receive BH
                const ulonglong2* s4 = reinterpret_cast<const ulonglong2*>(stB + warp * 128 + off);
                ulonglong2 a = s4[0], b = s4[1];
                B[0]=a.x; B[1]=a.y; B[2]=b.x; B[3]=b.y;
            }
        }

        int active = s_flag;
        __syncthreads();
        if (!active) break;
    }

    // ---- norms -> eigenvalues; normalized columns -> SH (order-free) ----
    {
        const int k = warp * 4 + team;
        u64 dpp2 = mul2(T[0], T[0]);
        u64 dqq2 = mul2(B[0], B[0]);
        #pragma unroll
        for (int i = 1; i < 4; ++i) {
            dpp2 = fma2(T[i], T[i], dpp2);
            dqq2 = fma2(B[i], B[i], dqq2);
        }
        float dpp = hadd2(dpp2);
        float dqq = hadd2(dqq2);
        #pragma unroll
        for (int o = 4; o; o >>= 1) {
            dpp += __shfl_xor_sync(tm, dpp, o);
            dqq += __shfl_xor_sync(tm, dqq, o);
        }
        float it = (dpp > 1e-30f) ? rsqrtf(dpp) : 0.0f;
        float ib = (dqq > 1e-30f) ? rsqrtf(dqq) : 0.0f;
        u64 it2 = pack2(it, it), ib2 = pack2(ib, ib);
        ulonglong2* mt = reinterpret_cast<ulonglong2*>(SH + (2 * k) * 64 + sl * 8);
        ulonglong2* mb = reinterpret_cast<ulonglong2*>(SH + (2 * k + 1) * 64 + sl * 8);
        mt[0] = make_ulonglong2(mul2(it2, T[0]), mul2(it2, T[1]));
        mt[1] = make_ulonglong2(mul2(it2, T[2]), mul2(it2, T[3]));
        mb[0] = make_ulonglong2(mul2(ib2, B[0]), mul2(ib2, B[1]));
        mb[1] = make_ulonglong2(mul2(ib2, B[2]), mul2(ib2, B[3]));
        if (sl == 0) {
            wlog[2 * k]     = 0.5f * logf(fmaxf(dpp, EPSV2));
            wlog[2 * k + 1] = 0.5f * logf(fmaxf(dqq, EPSV2));
        }
    }
    __syncthreads();

    // ---- O = U diag(w) U^T, 4x4 register tile per thread ----
    const int ta = tid >> 4;
    const int tb = tid & 15;
    float acc[4][4];
    #pragma unroll
    for (int i = 0; i < 4; ++i)
        #pragma unroll
        for (int j = 0; j < 4; ++j) acc[i][j] = 0.0f;

    for (int kk = 0; kk < 64; ++kk) {
        float w = wlog[kk];
        float4 ur = *reinterpret_cast<const float4*>(SH + kk * 64 + 4 * ta);
        float4 uc = *reinterpret_cast<const float4*>(SH + kk * 64 + 4 * tb);
        float r0 = w * ur.x, r1 = w * ur.y, r2 = w * ur.z, r3 = w * ur.w;
        acc[0][0] += r0 * uc.x; acc[0][1] += r0 * uc.y; acc[0][2] += r0 * uc.z; acc[0][3] += r0 * uc.w;
        acc[1][0] += r1 * uc.x; acc[1][1] += r1 * uc.y; acc[1][2] += r1 * uc.z; acc[1][3] += r1 * uc.w;
        acc[2][0] += r2 * uc.x; acc[2][1] += r2 * uc.y; acc[2][2] += r2 * uc.z; acc[2][3] += r2 * uc.w;
        acc[3][0] += r3 * uc.x; acc[3][1] += r3 * uc.y; acc[3][2] += r3 * uc.z; acc[3][3] += r3 * uc.w;
    }

    float* go = out + base;
    #pragma unroll
    for (int i = 0; i < 4; ++i) {
        float4 v = make_float4(acc[i][0], acc[i][1], acc[i][2], acc[i][3]);
        *reinterpret_cast<float4*>(go + (4 * ta + i) * 64 + 4 * tb) = v;
    }
#undef VISIT
}

extern "C" void kernel_launch(void* const* d_in, const int* in_sizes, int n_in,
                              void* d_out, int out_size)
{
    const float* x = (const float*)d_in[0];
    float* out = (float*)d_out;
    int batches = in_sizes[0] / 4096;
    logm_jacobi_kernel<<<batches, 256>>>(x, out);
}

// round 11
// speedup vs baseline: 1.0729x; 1.0242x over previous
#include <cuda_runtime.h>

#define EPSV2    1e-8f         // EPSV^2
#define TOLSQ    1e-8f         // (1e-4)^2 relative orthogonality threshold
#define MAXSWEEP 30
#define FULLM    0xffffffffu

typedef unsigned long long u64;

// ---- packed f32x2 helpers (sm_10x; ptxas never emits these from C++) ----
__device__ __forceinline__ u64 mul2(u64 a, u64 b) {
    u64 r; asm("mul.rn.f32x2 %0, %1, %2;" : "=l"(r) : "l"(a), "l"(b)); return r;
}
__device__ __forceinline__ u64 fma2(u64 a, u64 b, u64 c) {
    u64 r; asm("fma.rn.f32x2 %0, %1, %2, %3;" : "=l"(r) : "l"(a), "l"(b), "l"(c)); return r;
}
__device__ __forceinline__ u64 pack2(float lo, float hi) {
    u64 r; asm("mov.b64 %0, {%1, %2};" : "=l"(r) : "f"(lo), "f"(hi)); return r;
}
__device__ __forceinline__ float hadd2(u64 a) {
    float lo, hi; asm("mov.b64 {%0, %1}, %2;" : "=f"(lo), "=f"(hi) : "l"(a));
    return lo + hi;
}

// One CTA per 64x64 SPD matrix. One-sided Jacobi, register-resident packed
// columns, hierarchical tournament (R8/R10 structure — validated best).
// R11: (a) __launch_bounds__(256,5) — reg cap 51 (audited ~47 live), occupancy
// 49% -> 61% to fill shfl-latency/barrier slack; (b) tol 3e-5 -> 1e-4 per the
// measured error-vs-tol curve (predicted rel_err ~3e-4, 3x under gate).
__global__ void __launch_bounds__(256, 5)
logm_jacobi_kernel(const float* __restrict__ in, float* __restrict__ out)
{
    __shared__ __align__(16) float SH[8192];   // staging; epilogue U matrix
    __shared__ float wlog[64];
    __shared__ int   s_flag;

    const int tid  = threadIdx.x;
    const int lane = tid & 31;
    const int warp = tid >> 5;
    const int team = lane >> 3;               // 4 teams per warp
    const int sl   = lane & 7;                // lane within team
    const unsigned tm = 0xffu << (team << 3); // team shfl mask
    const size_t base = (size_t)blockIdx.x * 4096;

    // pair visit: 3 packed dots (independent chains) + butterfly + rotation
#define VISIT(TT, BB)                                                        \
    {                                                                        \
        u64 dpq2 = mul2(TT[0], BB[0]);                                       \
        u64 dpp2 = mul2(TT[0], TT[0]);                                       \
        u64 dqq2 = mul2(BB[0], BB[0]);                                       \
        _Pragma("unroll")                                                    \
        for (int i = 1; i < 4; ++i) {                                        \
            dpq2 = fma2(TT[i], BB[i], dpq2);                                 \
            dpp2 = fma2(TT[i], TT[i], dpp2);                                 \
            dqq2 = fma2(BB[i], BB[i], dqq2);                                 \
        }                                                                    \
        float dpq = hadd2(dpq2);                                             \
        float dpp = hadd2(dpp2);                                             \
        float dqq = hadd2(dqq2);                                             \
        _Pragma("unroll")                                                    \
        for (int o = 4; o; o >>= 1) {                                        \
            dpq += __shfl_xor_sync(tm, dpq, o);                              \
            dpp += __shfl_xor_sync(tm, dpp, o);                              \
            dqq += __shfl_xor_sync(tm, dqq, o);                              \
        }                                                                    \
        if (dpq * dpq > TOLSQ * dpp * dqq) {                                 \
            float tau = __fdividef(dqq - dpp, 2.0f * dpq);                   \
            float t = copysignf(1.0f, tau) /                                 \
                      (fabsf(tau) + sqrtf(1.0f + tau * tau));                \
            float c = rsqrtf(1.0f + t * t);                                  \
            float s = t * c;                                                 \
            u64 c2  = pack2(c, c);                                           \
            u64 s2  = pack2(s, s);                                           \
            u64 ms2 = pack2(-s, -s);                                         \
            _Pragma("unroll")                                                \
            for (int i = 0; i < 4; ++i) {                                    \
                u64 tp = fma2(ms2, BB[i], mul2(c2, TT[i]));                  \
                BB[i]  = fma2(s2,  TT[i], mul2(c2, BB[i]));                  \
                TT[i]  = tp;                                                 \
            }                                                                \
            if (sl == 0) s_flag = 1;                                         \
        }                                                                    \
    }

    // ---- load: warp w team t holds cols 4w+t (T) and 32+4w+t (B) ----
    u64 T[4], B[4];
    {
        const int c = warp * 4 + team;
        const ulonglong2* gt = reinterpret_cast<const ulonglong2*>(in + base + c * 64 + sl * 8);
        const ulonglong2* gb = reinterpret_cast<const ulonglong2*>(in + base + (32 + c) * 64 + sl * 8);
        ulonglong2 t0 = gt[0], t1 = gt[1], b0 = gb[0], b1 = gb[1];
        T[0]=t0.x; T[1]=t0.y; T[2]=t1.x; T[3]=t1.y;
        B[0]=b0.x; B[1]=b0.y; B[2]=b1.x; B[3]=b1.y;
    }

    const int rotsrc = (lane + 8) & 31;       // +1-team rotation source

    for (int sweep = 0; sweep < MAXSWEEP; ++sweep) {
        if (tid == 0) s_flag = 0;
        __syncthreads();

        for (int outer = 0; outer < 15; ++outer) {
            // ---- 4 inner cross rounds (intra-warp only) ----
            #pragma unroll
            for (int rho = 0; rho < 4; ++rho) {
                VISIT(T, B);
                #pragma unroll
                for (int i = 0; i < 4; ++i)      // rotate B one team
                    B[i] = __shfl_sync(FULLM, B[i], rotsrc);
            }

            // ---- intra-half pairs, once per sweep ----
            if (outer == 0) {
                // gather: t0:(tc0,tc1) t1:(tc2,tc3) t2:(bc0,bc1) t3:(bc2,bc3)
                const int sTA = (team == 1) ? rotsrc : lane;
                const int sBA = (team == 2) ? ((lane + 16) & 31) : ((lane + 24) & 31);
                const int sTB = (team == 0) ? rotsrc : ((lane + 16) & 31);
                const int sBB = (team == 2) ? ((lane + 24) & 31) : lane;
                #pragma unroll
                for (int i = 0; i < 4; ++i) {
                    u64 tA = __shfl_sync(FULLM, T[i], sTA);
                    u64 bA = __shfl_sync(FULLM, B[i], sBA);
                    u64 tB = __shfl_sync(FULLM, T[i], sTB);
                    u64 bB = __shfl_sync(FULLM, B[i], sBB);
                    T[i] = (team < 2) ? tA : bA;
                    B[i] = (team < 2) ? tB : bB;
                }
                VISIT(T, B);
                {   // swap1: even.B <-> odd.T (xor 8)
                    const bool ev = ((team & 1) == 0);
                    #pragma unroll
                    for (int i = 0; i < 4; ++i) {
                        u64 tx = __shfl_xor_sync(FULLM, T[i], 8);
                        u64 bx = __shfl_xor_sync(FULLM, B[i], 8);
                        u64 nB = ev ? tx : B[i];
                        u64 nT = ev ? T[i] : bx;
                        T[i] = nT; B[i] = nB;
                    }
                }
                VISIT(T, B);
                #pragma unroll
                for (int i = 0; i < 4; ++i)      // swap2: B <-> B (xor 8)
                    B[i] = __shfl_xor_sync(FULLM, B[i], 8);
                VISIT(T, B);
                // restore home: t:(tc_t, bc_t)
                const int rT = (team == 2) ? ((lane + 24) & 31) : rotsrc;
                const int rB = (team == 2) ? rotsrc : ((lane + 24) & 31);
                const int r16 = (lane + 16) & 31;
                #pragma unroll
                for (int i = 0; i < 4; ++i) {
                    u64 rb  = __shfl_sync(FULLM, B[i], rT);
                    u64 rt  = __shfl_sync(FULLM, T[i], r16);
                    u64 rb2 = __shfl_sync(FULLM, B[i], rB);
                    T[i] = (team < 2) ? T[i] : rb;
                    B[i] = (team < 2) ? rt   : rb2;
                }
            }

            // ---- outer rotation: half-blocks through the ring via staging ----
            u64* st  = reinterpret_cast<u64*>(SH) + (outer & 1) * 2048;
            u64* stT = st;                         // [warp][128] u64
            u64* stB = st + 1024;
            const int off = team * 32 + sl * 4;    // u64 units
            if (warp >= 1 && warp <= 6) {          // TH -> warp+1
                ulonglong2* d = reinterpret_cast<ulonglong2*>(stT + (warp + 1) * 128 + off);
                d[0] = make_ulonglong2(T[0], T[1]);
                d[1] = make_ulonglong2(T[2], T[3]);
            }
            if (warp == 0) {                       // BH_0 -> warp1's TH
                ulonglong2* d = reinterpret_cast<ulonglong2*>(stT + 1 * 128 + off);
                d[0] = make_ulonglong2(B[0], B[1]);
                d[1] = make_ulonglong2(B[2], B[3]);
            }
            if (warp >= 1) {                       // BH -> warp-1
                ulonglong2* d = reinterpret_cast<ulonglong2*>(stB + (warp - 1) * 128 + off);
                d[0] = make_ulonglong2(B[0], B[1]);
                d[1] = make_ulonglong2(B[2], B[3]);
            }
            if (warp == 7) {                       // TH_7 -> own BH
                #pragma unroll
                for (int i = 0; i < 4; ++i) B[i] = T[i];
            }
            __syncthreads();
            if (warp >= 1) {                       // receive TH
                const ulonglong2* s4 = reinterpret_cast<const ulonglong2*>(stT + warp * 128 + off);
                ulonglong2 a = s4[0], b = s4[1];
                T[0]=a.x; T[1]=a.y; T[2]=b.x; T[3]=b.y;
            }
            if (warp <= 6) {                       // receive BH
                const ulonglong2* s4 = reinterpret_cast<const ulonglong2*>(stB + warp * 128 + off);
                ulonglong2 a = s4[0], b = s4[1];
                B[0]=a.x; B[1]=a.y; B[2]=b.x; B[3]=b.y;
            }
        }

        int active = s_flag;
        __syncthreads();
        if (!active) break;
    }

    // ---- norms -> eigenvalues; normalized columns -> SH (order-free) ----
    {
        const int k = warp * 4 + team;
        u64 dpp2 = mul2(T[0], T[0]);
        u64 dqq2 = mul2(B[0], B[0]);
        #pragma unroll
        for (int i = 1; i < 4; ++i) {
            dpp2 = fma2(T[i], T[i], dpp2);
            dqq2 = fma2(B[i], B[i], dqq2);
        }
        float dpp = hadd2(dpp2);
        float dqq = hadd2(dqq2);
        #pragma unroll
        for (int o = 4; o; o >>= 1) {
            dpp += __shfl_xor_sync(tm, dpp, o);
            dqq += __shfl_xor_sync(tm, dqq, o);
        }
        float it = (dpp > 1e-30f) ? rsqrtf(dpp) : 0.0f;
        float ib = (dqq > 1e-30f) ? rsqrtf(dqq) : 0.0f;
        u64 it2 = pack2(it, it), ib2 = pack2(ib, ib);
        ulonglong2* mt = reinterpret_cast<ulonglong2*>(SH + (2 * k) * 64 + sl * 8);
        ulonglong2* mb = reinterpret_cast<ulonglong2*>(SH + (2 * k + 1) * 64 + sl * 8);
        mt[0] = make_ulonglong2(mul2(it2, T[0]), mul2(it2, T[1]));
        mt[1] = make_ulonglong2(mul2(it2, T[2]), mul2(it2, T[3]));
        mb[0] = make_ulonglong2(mul2(ib2, B[0]), mul2(ib2, B[1]));
        mb[1] = make_ulonglong2(mul2(ib2, B[2]), mul2(ib2, B[3]));
        if (sl == 0) {
            wlog[2 * k]     = 0.5f * logf(fmaxf(dpp, EPSV2));
            wlog[2 * k + 1] = 0.5f * logf(fmaxf(dqq, EPSV2));
        }
    }
    __syncthreads();

    // ---- O = U diag(w) U^T, 4x4 register tile per thread ----
    const int ta = tid >> 4;
    const int tb = tid & 15;
    float acc[4][4];
    #pragma unroll
    for (int i = 0; i < 4; ++i)
        #pragma unroll
        for (int j = 0; j < 4; ++j) acc[i][j] = 0.0f;

    for (int kk = 0; kk < 64; ++kk) {
        float w = wlog[kk];
        float4 ur = *reinterpret_cast<const float4*>(SH + kk * 64 + 4 * ta);
        float4 uc = *reinterpret_cast<const float4*>(SH + kk * 64 + 4 * tb);
        float r0 = w * ur.x, r1 = w * ur.y, r2 = w * ur.z, r3 = w * ur.w;
        acc[0][0] += r0 * uc.x; acc[0][1] += r0 * uc.y; acc[0][2] += r0 * uc.z; acc[0][3] += r0 * uc.w;
        acc[1][0] += r1 * uc.x; acc[1][1] += r1 * uc.y; acc[1][2] += r1 * uc.z; acc[1][3] += r1 * uc.w;
        acc[2][0] += r2 * uc.x; acc[2][1] += r2 * uc.y; acc[2][2] += r2 * uc.z; acc[2][3] += r2 * uc.w;
        acc[3][0] += r3 * uc.x; acc[3][1] += r3 * uc.y; acc[3][2] += r3 * uc.z; acc[3][3] += r3 * uc.w;
    }

    float* go = out + base;
    #pragma unroll
    for (int i = 0; i < 4; ++i) {
        float4 v = make_float4(acc[i][0], acc[i][1], acc[i][2], acc[i][3]);
        *reinterpret_cast<float4*>(go + (4 * ta + i) * 64 + 4 * tb) = v;
    }
#undef VISIT
}

extern "C" void kernel_launch(void* const* d_in, const int* in_sizes, int n_in,
                              void* d_out, int out_size)
{
    const float* x = (const float*)d_in[0];
    float* out = (float*)d_out;
    int batches = in_sizes[0] / 4096;
    logm_jacobi_kernel<<<batches, 256>>>(x, out);
}

// round 14
// speedup vs baseline: 1.0783x; 1.0050x over previous
#include <cuda_runtime.h>

#define EPSV2      1e-8f       // EPSV^2
#define TOLSQ      1e-8f       // (1e-4)^2 rotation threshold (R11, validated)
#define TOLSQ_FLAG 9e-8f       // (3e-4)^2 sweep-continuation threshold
#define MAXSWEEP   30
#define FULLM      0xffffffffu

typedef unsigned long long u64;

// ---- packed f32x2 helpers (sm_10x; ptxas never emits these from C++) ----
__device__ __forceinline__ u64 mul2(u64 a, u64 b) {
    u64 r; asm("mul.rn.f32x2 %0, %1, %2;" : "=l"(r) : "l"(a), "l"(b)); return r;
}
__device__ __forceinline__ u64 fma2(u64 a, u64 b, u64 c) {
    u64 r; asm("fma.rn.f32x2 %0, %1, %2, %3;" : "=l"(r) : "l"(a), "l"(b), "l"(c)); return r;
}
__device__ __forceinline__ u64 pack2(float lo, float hi) {
    u64 r; asm("mov.b64 %0, {%1, %2};" : "=l"(r) : "f"(lo), "f"(hi)); return r;
}
__device__ __forceinline__ float hadd2(u64 a) {
    float lo, hi; asm("mov.b64 {%0, %1}, %2;" : "=f"(lo), "=f"(hi) : "l"(a));
    return lo + hi;
}

// One CTA per 64x64 SPD matrix. One-sided Jacobi, register-resident packed
// columns, hierarchical tournament. R14 = R11 numerics with a TWO-TIER
// tolerance: rotate at cos > 1e-4 (unchanged — R12 proved these rotations are
// load-bearing), but continue sweeping only if some pair had cos > 3e-4.
// Rotation debris regenerates cos ~1e-4 forever (R11/R13 evidence: flag never
// cleared, tail converges at ~0.83x/sweep), which defeated per-CTA early
// exit; the flag tier sits above the debris ceiling so converged CTAs
// actually leave. If the ceiling estimate is wrong the kernel degenerates to
// exactly R11 (7108us, passing) — asymmetric bet.
__global__ void __launch_bounds__(256, 5)
logm_jacobi_kernel(const float* __restrict__ in, float* __restrict__ out)
{
    __shared__ __align__(16) float SH[8192];   // staging; epilogue U matrix
    __shared__ float wlog[64];
    __shared__ int   s_flag;

    const int tid  = threadIdx.x;
    const int lane = tid & 31;
    const int warp = tid >> 5;
    const int team = lane >> 3;               // 4 teams per warp
    const int sl   = lane & 7;                // lane within team
    const unsigned tm = 0xffu << (team << 3); // team shfl mask
    const size_t base = (size_t)blockIdx.x * 4096;

    // pair visit: 3 packed dots (independent chains) + butterfly + rotation
#define VISIT(TT, BB)                                                        \
    {                                                                        \
        u64 dpq2 = mul2(TT[0], BB[0]);                                       \
        u64 dpp2 = mul2(TT[0], TT[0]);                                       \
        u64 dqq2 = mul2(BB[0], BB[0]);                                       \
        _Pragma("unroll")                                                    \
        for (int i = 1; i < 4; ++i) {                                        \
            dpq2 = fma2(TT[i], BB[i], dpq2);                                 \
            dpp2 = fma2(TT[i], TT[i], dpp2);                                 \
            dqq2 = fma2(BB[i], BB[i], dqq2);                                 \
        }                                                                    \
        float dpq = hadd2(dpq2);                                             \
        float dpp = hadd2(dpp2);                                             \
        float dqq = hadd2(dqq2);                                             \
        _Pragma("unroll")                                                    \
        for (int o = 4; o; o >>= 1) {                                        \
            dpq += __shfl_xor_sync(tm, dpq, o);                              \
            dpp += __shfl_xor_sync(tm, dpp, o);                              \
            dqq += __shfl_xor_sync(tm, dqq, o);                              \
        }                                                                    \
        float dsq = dpq * dpq;                                               \
        float rel = dpp * dqq;                                               \
        if (dsq > TOLSQ * rel) {                                             \
            float tau = __fdividef(dqq - dpp, 2.0f * dpq);                   \
            float t = copysignf(1.0f, tau) /                                 \
                      (fabsf(tau) + sqrtf(1.0f + tau * tau));                \
            float c = rsqrtf(1.0f + t * t);                                  \
            float s = t * c;                                                 \
            u64 c2  = pack2(c, c);                                           \
            u64 s2  = pack2(s, s);                                           \
            u64 ms2 = pack2(-s, -s);                                         \
            _Pragma("unroll")                                                \
            for (int i = 0; i < 4; ++i) {                                    \
                u64 tp = fma2(ms2, BB[i], mul2(c2, TT[i]));                  \
                BB[i]  = fma2(s2,  TT[i], mul2(c2, BB[i]));                  \
                TT[i]  = tp;                                                 \
            }                                                                \
            if (sl == 0 && dsq > TOLSQ_FLAG * rel) s_flag = 1;               \
        }                                                                    \
    }

    // ---- load: warp w team t holds cols 4w+t (T) and 32+4w+t (B) ----
    u64 T[4], B[4];
    {
        const int c = warp * 4 + team;
        const ulonglong2* gt = reinterpret_cast<const ulonglong2*>(in + base + c * 64 + sl * 8);
        const ulonglong2* gb = reinterpret_cast<const ulonglong2*>(in + base + (32 + c) * 64 + sl * 8);
        ulonglong2 t0 = gt[0], t1 = gt[1], b0 = gb[0], b1 = gb[1];
        T[0]=t0.x; T[1]=t0.y; T[2]=t1.x; T[3]=t1.y;
        B[0]=b0.x; B[1]=b0.y; B[2]=b1.x; B[3]=b1.y;
    }

    const int rotsrc = (lane + 8) & 31;       // +1-team rotation source

    for (int sweep = 0; sweep < MAXSWEEP; ++sweep) {
        if (tid == 0) s_flag = 0;
        __syncthreads();

        for (int outer = 0; outer < 15; ++outer) {
            // ---- 4 inner cross rounds (intra-warp only) ----
            #pragma unroll
            for (int rho = 0; rho < 4; ++rho) {
                VISIT(T, B);
                #pragma unroll
                for (int i = 0; i < 4; ++i)      // rotate B one team
                    B[i] = __shfl_sync(FULLM, B[i], rotsrc);
            }

            // ---- intra-half pairs, once per sweep ----
            if (outer == 0) {
                // gather: t0:(tc0,tc1) t1:(tc2,tc3) t2:(bc0,bc1) t3:(bc2,bc3)
                const int sTA = (team == 1) ? rotsrc : lane;
                const int sBA = (team == 2) ? ((lane + 16) & 31) : ((lane + 24) & 31);
                const int sTB = (team == 0) ? rotsrc : ((lane + 16) & 31);
                const int sBB = (team == 2) ? ((lane + 24) & 31) : lane;
                #pragma unroll
                for (int i = 0; i < 4; ++i) {
                    u64 tA = __shfl_sync(FULLM, T[i], sTA);
                    u64 bA = __shfl_sync(FULLM, B[i], sBA);
                    u64 tB = __shfl_sync(FULLM, T[i], sTB);
                    u64 bB = __shfl_sync(FULLM, B[i], sBB);
                    T[i] = (team < 2) ? tA : bA;
                    B[i] = (team < 2) ? tB : bB;
                }
                VISIT(T, B);
                {   // swap1: even.B <-> odd.T (xor 8)
                    const bool ev = ((team & 1) == 0);
                    #pragma unroll
                    for (int i = 0; i < 4; ++i) {
                        u64 tx = __shfl_xor_sync(FULLM, T[i], 8);
                        u64 bx = __shfl_xor_sync(FULLM, B[i], 8);
                        u64 nB = ev ? tx : B[i];
                        u64 nT = ev ? T[i] : bx;
                        T[i] = nT; B[i] = nB;
                    }
                }
                VISIT(T, B);
                #pragma unroll
                for (int i = 0; i < 4; ++i)      // swap2: B <-> B (xor 8)
                    B[i] = __shfl_xor_sync(FULLM, B[i], 8);
                VISIT(T, B);
                // restore home: t:(tc_t, bc_t)
                const int rT = (team == 2) ? ((lane + 24) & 31) : rotsrc;
                const int rB = (team == 2) ? rotsrc : ((lane + 24) & 31);
                const int r16 = (lane + 16) & 31;
                #pragma unroll
                for (int i = 0; i < 4; ++i) {
                    u64 rb  = __shfl_sync(FULLM, B[i], rT);
                    u64 rt  = __shfl_sync(FULLM, T[i], r16);
                    u64 rb2 = __shfl_sync(FULLM, B[i], rB);
                    T[i] = (team < 2) ? T[i] : rb;
                    B[i] = (team < 2) ? rt   : rb2;
                }
            }

            // ---- outer rotation: half-blocks through the ring via staging ----
            u64* st  = reinterpret_cast<u64*>(SH) + (outer & 1) * 2048;
            u64* stT = st;                         // [warp][128] u64
            u64* stB = st + 1024;
            const int off = team * 32 + sl * 4;    // u64 units
            if (warp >= 1 && warp <= 6) {          // TH -> warp+1
                ulonglong2* d = reinterpret_cast<ulonglong2*>(stT + (warp + 1) * 128 + off);
                d[0] = make_ulonglong2(T[0], T[1]);
                d[1] = make_ulonglong2(T[2], T[3]);
            }
            if (warp == 0) {                       // BH_0 -> warp1's TH
                ulonglong2* d = reinterpret_cast<ulonglong2*>(stT + 1 * 128 + off);
                d[0] = make_ulonglong2(B[0], B[1]);
                d[1] = make_ulonglong2(B[2], B[3]);
            }
            if (warp >= 1) {                       // BH -> warp-1
                ulonglong2* d = reinterpret_cast<ulonglong2*>(stB + (warp - 1) * 128 + off);
                d[0] = make_ulonglong2(B[0], B[1]);
                d[1] = make_ulonglong2(B[2], B[3]);
            }
            if (warp == 7) {                       // TH_7 -> own BH
                #pragma unroll
                for (int i = 0; i < 4; ++i) B[i] = T[i];
            }
            __syncthreads();
            if (warp >= 1) {                       // receive TH
                const ulonglong2* s4 = reinterpret_cast<const ulonglong2*>(stT + warp * 128 + off);
                ulonglong2 a = s4[0], b = s4[1];
                T[0]=a.x; T[1]=a.y; T[2]=b.x; T[3]=b.y;
            }
            if (warp <= 6) {                       // receive BH
                const ulonglong2* s4 = reinterpret_cast<const ulonglong2*>(stB + warp * 128 + off);
                ulonglong2 a = s4[0], b = s4[1];
                B[0]=a.x; B[1]=a.y; B[2]=b.x; B[3]=b.y;
            }
        }

        int active = s_flag;
        __syncthreads();
        if (!active) break;
    }

    // ---- norms -> eigenvalues; normalized columns -> SH (order-free) ----
    {
        const int k = warp * 4 + team;
        u64 dpp2 = mul2(T[0], T[0]);
        u64 dqq2 = mul2(B[0], B[0]);
        #pragma unroll
        for (int i = 1; i < 4; ++i) {
            dpp2 = fma2(T[i], T[i], dpp2);
            dqq2 = fma2(B[i], B[i], dqq2);
        }
        float dpp = hadd2(dpp2);
        float dqq = hadd2(dqq2);
        #pragma unroll
        for (int o = 4; o; o >>= 1) {
            dpp += __shfl_xor_sync(tm, dpp, o);
            dqq += __shfl_xor_sync(tm, dqq, o);
        }
        float it = (dpp > 1e-30f) ? rsqrtf(dpp) : 0.0f;
        float ib = (dqq > 1e-30f) ? rsqrtf(dqq) : 0.0f;
        u64 it2 = pack2(it, it), ib2 = pack2(ib, ib);
        ulonglong2* mt = reinterpret_cast<ulonglong2*>(SH + (2 * k) * 64 + sl * 8);
        ulonglong2* mb = reinterpret_cast<ulonglong2*>(SH + (2 * k + 1) * 64 + sl * 8);
        mt[0] = make_ulonglong2(mul2(it2, T[0]), mul2(it2, T[1]));
        mt[1] = make_ulonglong2(mul2(it2, T[2]), mul2(it2, T[3]));
        mb[0] = make_ulonglong2(mul2(ib2, B[0]), mul2(ib2, B[1]));
        mb[1] = make_ulonglong2(mul2(ib2, B[2]), mul2(ib2, B[3]));
        if (sl == 0) {
            wlog[2 * k]     = 0.5f * logf(fmaxf(dpp, EPSV2));
            wlog[2 * k + 1] = 0.5f * logf(fmaxf(dqq, EPSV2));
        }
    }
    __syncthreads();

    // ---- O = U diag(w) U^T, 4x4 register tile per thread ----
    const int ta = tid >> 4;
    const int tb = tid & 15;
    float acc[4][4];
    #pragma unroll
    for (int i = 0; i < 4; ++i)
        #pragma unroll
        for (int j = 0; j < 4; ++j) acc[i][j] = 0.0f;

    for (int kk = 0; kk < 64; ++kk) {
        float w = wlog[kk];
        float4 ur = *reinterpret_cast<const float4*>(SH + kk * 64 + 4 * ta);
        float4 uc = *reinterpret_cast<const float4*>(SH + kk * 64 + 4 * tb);
        float r0 = w * ur.x, r1 = w * ur.y, r2 = w * ur.z, r3 = w * ur.w;
        acc[0][0] += r0 * uc.x; acc[0][1] += r0 * uc.y; acc[0][2] += r0 * uc.z; acc[0][3] += r0 * uc.w;
        acc[1][0] += r1 * uc.x; acc[1][1] += r1 * uc.y; acc[1][2] += r1 * uc.z; acc[1][3] += r1 * uc.w;
        acc[2][0] += r2 * uc.x; acc[2][1] += r2 * uc.y; acc[2][2] += r2 * uc.z; acc[2][3] += r2 * uc.w;
        acc[3][0] += r3 * uc.x; acc[3][1] += r3 * uc.y; acc[3][2] += r3 * uc.z; acc[3][3] += r3 * uc.w;
    }

    float* go = out + base;
    #pragma unroll
    for (int i = 0; i < 4; ++i) {
        float4 v = make_float4(acc[i][0], acc[i][1], acc[i][2], acc[i][3]);
        *reinterpret_cast<float4*>(go + (4 * ta + i) * 64 + 4 * tb) = v;
    }
#undef VISIT
}

extern "C" void kernel_launch(void* const* d_in, const int* in_sizes, int n_in,
                              void* d_out, int out_size)
{
    const float* x = (const float*)d_in[0];
    float* out = (float*)d_out;
    int batches = in_sizes[0] / 4096;
    logm_jacobi_kernel<<<batches, 256>>>(x, out);
}

// round 15
// speedup vs baseline: 1.0786x; 1.0004x over previous
#include <cuda_runtime.h>

#define EPSV2      1e-8f       // EPSV^2
#define TOLSQ      1e-8f       // (1e-4)^2 rotation threshold (R11, validated)
#define TOLSQ_FLAG 9e-8f       // (3e-4)^2 sweep-continuation threshold
#define MAXSWEEP   18
#define FULLM      0xffffffffu

typedef unsigned long long u64;

// ---- packed f32x2 helpers (sm_10x; ptxas never emits these from C++) ----
__device__ __forceinline__ u64 mul2(u64 a, u64 b) {
    u64 r; asm("mul.rn.f32x2 %0, %1, %2;" : "=l"(r) : "l"(a), "l"(b)); return r;
}
__device__ __forceinline__ u64 fma2(u64 a, u64 b, u64 c) {
    u64 r; asm("fma.rn.f32x2 %0, %1, %2, %3;" : "=l"(r) : "l"(a), "l"(b), "l"(c)); return r;
}
__device__ __forceinline__ u64 pack2(float lo, float hi) {
    u64 r; asm("mov.b64 %0, {%1, %2};" : "=l"(r) : "f"(lo), "f"(hi)); return r;
}
__device__ __forceinline__ float hadd2(u64 a) {
    float lo, hi; asm("mov.b64 {%0, %1}, %2;" : "=f"(lo), "=f"(hi) : "l"(a));
    return lo + hi;
}

// One CTA per 64x64 SPD matrix. One-sided Jacobi, register-resident packed
// columns, hierarchical tournament. R15 = R14 with MAXSWEEP 30 -> 18.
// Evidence chain: R14's rel_err is BIT-IDENTICAL to R11's -> the continuation
// flag never clears (fp32 debris keeps big/small pairs at cos ~1e-3 forever),
// so MAXSWEEP is the terminator. Final error at 30 sweeps scales linearly
// with tol across 3 tested tolerances -> 30 sweeps is past the convergence
// floor; 12 sweeps (8.9e-3) is before it; Jacobi's quadratic endgame puts the
// floor-crossing at ~15-16 sweeps. 18 = floor + margin for the worst of 8192.
__global__ void __launch_bounds__(256, 5)
logm_jacobi_kernel(const float* __restrict__ in, float* __restrict__ out)
{
    __shared__ __align__(16) float SH[8192];   // staging; epilogue U matrix
    __shared__ float wlog[64];
    __shared__ int   s_flag;

    const int tid  = threadIdx.x;
    const int lane = tid & 31;
    const int warp = tid >> 5;
    const int team = lane >> 3;               // 4 teams per warp
    const int sl   = lane & 7;                // lane within team
    const unsigned tm = 0xffu << (team << 3); // team shfl mask
    const size_t base = (size_t)blockIdx.x * 4096;

    // pair visit: 3 packed dots (independent chains) + butterfly + rotation
#define VISIT(TT, BB)                                                        \
    {                                                                        \
        u64 dpq2 = mul2(TT[0], BB[0]);                                       \
        u64 dpp2 = mul2(TT[0], TT[0]);                                       \
        u64 dqq2 = mul2(BB[0], BB[0]);                                       \
        _Pragma("unroll")                                                    \
        for (int i = 1; i < 4; ++i) {                                        \
            dpq2 = fma2(TT[i], BB[i], dpq2);                                 \
            dpp2 = fma2(TT[i], TT[i], dpp2);                                 \
            dqq2 = fma2(BB[i], BB[i], dqq2);                                 \
        }                                                                    \
        float dpq = hadd2(dpq2);                                             \
        float dpp = hadd2(dpp2);                                             \
        float dqq = hadd2(dqq2);                                             \
        _Pragma("unroll")                                                    \
        for (int o = 4; o; o >>= 1) {                                        \
            dpq += __shfl_xor_sync(tm, dpq, o);                              \
            dpp += __shfl_xor_sync(tm, dpp, o);                              \
            dqq += __shfl_xor_sync(tm, dqq, o);                              \
        }                                                                    \
        float dsq = dpq * dpq;                                               \
        float rel = dpp * dqq;                                               \
        if (dsq > TOLSQ * rel) {                                             \
            float tau = __fdividef(dqq - dpp, 2.0f * dpq);                   \
            float t = copysignf(1.0f, tau) /                                 \
                      (fabsf(tau) + sqrtf(1.0f + tau * tau));                \
            float c = rsqrtf(1.0f + t * t);                                  \
            float s = t * c;                                                 \
            u64 c2  = pack2(c, c);                                           \
            u64 s2  = pack2(s, s);                                           \
            u64 ms2 = pack2(-s, -s);                                         \
            _Pragma("unroll")                                                \
            for (int i = 0; i < 4; ++i) {                                    \
                u64 tp = fma2(ms2, BB[i], mul2(c2, TT[i]));                  \
                BB[i]  = fma2(s2,  TT[i], mul2(c2, BB[i]));                  \
                TT[i]  = tp;                                                 \
            }                                                                \
            if (sl == 0 && dsq > TOLSQ_FLAG * rel) s_flag = 1;               \
        }                                                                    \
    }

    // ---- load: warp w team t holds cols 4w+t (T) and 32+4w+t (B) ----
    u64 T[4], B[4];
    {
        const int c = warp * 4 + team;
        const ulonglong2* gt = reinterpret_cast<const ulonglong2*>(in + base + c * 64 + sl * 8);
        const ulonglong2* gb = reinterpret_cast<const ulonglong2*>(in + base + (32 + c) * 64 + sl * 8);
        ulonglong2 t0 = gt[0], t1 = gt[1], b0 = gb[0], b1 = gb[1];
        T[0]=t0.x; T[1]=t0.y; T[2]=t1.x; T[3]=t1.y;
        B[0]=b0.x; B[1]=b0.y; B[2]=b1.x; B[3]=b1.y;
    }

    const int rotsrc = (lane + 8) & 31;       // +1-team rotation source

    for (int sweep = 0; sweep < MAXSWEEP; ++sweep) {
        if (tid == 0) s_flag = 0;
        __syncthreads();

        for (int outer = 0; outer < 15; ++outer) {
            // ---- 4 inner cross rounds (intra-warp only) ----
            #pragma unroll
            for (int rho = 0; rho < 4; ++rho) {
                VISIT(T, B);
                #pragma unroll
                for (int i = 0; i < 4; ++i)      // rotate B one team
                    B[i] = __shfl_sync(FULLM, B[i], rotsrc);
            }

            // ---- intra-half pairs, once per sweep ----
            if (outer == 0) {
                // gather: t0:(tc0,tc1) t1:(tc2,tc3) t2:(bc0,bc1) t3:(bc2,bc3)
                const int sTA = (team == 1) ? rotsrc : lane;
                const int sBA = (team == 2) ? ((lane + 16) & 31) : ((lane + 24) & 31);
                const int sTB = (team == 0) ? rotsrc : ((lane + 16) & 31);
                const int sBB = (team == 2) ? ((lane + 24) & 31) : lane;
                #pragma unroll
                for (int i = 0; i < 4; ++i) {
                    u64 tA = __shfl_sync(FULLM, T[i], sTA);
                    u64 bA = __shfl_sync(FULLM, B[i], sBA);
                    u64 tB = __shfl_sync(FULLM, T[i], sTB);
                    u64 bB = __shfl_sync(FULLM, B[i], sBB);
                    T[i] = (team < 2) ? tA : bA;
                    B[i] = (team < 2) ? tB : bB;
                }
                VISIT(T, B);
                {   // swap1: even.B <-> odd.T (xor 8)
                    const bool ev = ((team & 1) == 0);
                    #pragma unroll
                    for (int i = 0; i < 4; ++i) {
                        u64 tx = __shfl_xor_sync(FULLM, T[i], 8);
                        u64 bx = __shfl_xor_sync(FULLM, B[i], 8);
                        u64 nB = ev ? tx : B[i];
                        u64 nT = ev ? T[i] : bx;
                        T[i] = nT; B[i] = nB;
                    }
                }
                VISIT(T, B);
                #pragma unroll
                for (int i = 0; i < 4; ++i)      // swap2: B <-> B (xor 8)
                    B[i] = __shfl_xor_sync(FULLM, B[i], 8);
                VISIT(T, B);
                // restore home: t:(tc_t, bc_t)
                const int rT = (team == 2) ? ((lane + 24) & 31) : rotsrc;
                const int rB = (team == 2) ? rotsrc : ((lane + 24) & 31);
                const int r16 = (lane + 16) & 31;
                #pragma unroll
                for (int i = 0; i < 4; ++i) {
                    u64 rb  = __shfl_sync(FULLM, B[i], rT);
                    u64 rt  = __shfl_sync(FULLM, T[i], r16);
                    u64 rb2 = __shfl_sync(FULLM, B[i], rB);
                    T[i] = (team < 2) ? T[i] : rb;
                    B[i] = (team < 2) ? rt   : rb2;
                }
            }

            // ---- outer rotation: half-blocks through the ring via staging ----
            u64* st  = reinterpret_cast<u64*>(SH) + (outer & 1) * 2048;
            u64* stT = st;                         // [warp][128] u64
            u64* stB = st + 1024;
            const int off = team * 32 + sl * 4;    // u64 units
            if (warp >= 1 && warp <= 6) {          // TH -> warp+1
                ulonglong2* d = reinterpret_cast<ulonglong2*>(stT + (warp + 1) * 128 + off);
                d[0] = make_ulonglong2(T[0], T[1]);
                d[1] = make_ulonglong2(T[2], T[3]);
            }
            if (warp == 0) {                       // BH_0 -> warp1's TH
                ulonglong2* d = reinterpret_cast<ulonglong2*>(stT + 1 * 128 + off);
                d[0] = make_ulonglong2(B[0], B[1]);
                d[1] = make_ulonglong2(B[2], B[3]);
            }
            if (warp >= 1) {                       // BH -> warp-1
                ulonglong2* d = reinterpret_cast<ulonglong2*>(stB + (warp - 1) * 128 + off);
                d[0] = make_ulonglong2(B[0], B[1]);
                d[1] = make_ulonglong2(B[2], B[3]);
            }
            if (warp == 7) {                       // TH_7 -> own BH
                #pragma unroll
                for (int i = 0; i < 4; ++i) B[i] = T[i];
            }
            __syncthreads();
            if (warp >= 1) {                       // receive TH
                const ulonglong2* s4 = reinterpret_cast<const ulonglong2*>(stT + warp * 128 + off);
                ulonglong2 a = s4[0], b = s4[1];
                T[0]=a.x; T[1]=a.y; T[2]=b.x; T[3]=b.y;
            }
            if (warp <= 6) {                       // receive BH
                const ulonglong2* s4 = reinterpret_cast<const ulonglong2*>(stB + warp * 128 + off);
                ulonglong2 a = s4[0], b = s4[1];
                B[0]=a.x; B[1]=a.y; B[2]=b.x; B[3]=b.y;
            }
        }

        int active = s_flag;
        __syncthreads();
        if (!active) break;
    }

    // ---- norms -> eigenvalues; normalized columns -> SH (order-free) ----
    {
        const int k = warp * 4 + team;
        u64 dpp2 = mul2(T[0], T[0]);
        u64 dqq2 = mul2(B[0], B[0]);
        #pragma unroll
        for (int i = 1; i < 4; ++i) {
            dpp2 = fma2(T[i], T[i], dpp2);
            dqq2 = fma2(B[i], B[i], dqq2);
        }
        float dpp = hadd2(dpp2);
        float dqq = hadd2(dqq2);
        #pragma unroll
        for (int o = 4; o; o >>= 1) {
            dpp += __shfl_xor_sync(tm, dpp, o);
            dqq += __shfl_xor_sync(tm, dqq, o);
        }
        float it = (dpp > 1e-30f) ? rsqrtf(dpp) : 0.0f;
        float ib = (dqq > 1e-30f) ? rsqrtf(dqq) : 0.0f;
        u64 it2 = pack2(it, it), ib2 = pack2(ib, ib);
        ulonglong2* mt = reinterpret_cast<ulonglong2*>(SH + (2 * k) * 64 + sl * 8);
        ulonglong2* mb = reinterpret_cast<ulonglong2*>(SH + (2 * k + 1) * 64 + sl * 8);
        mt[0] = make_ulonglong2(mul2(it2, T[0]), mul2(it2, T[1]));
        mt[1] = make_ulonglong2(mul2(it2, T[2]), mul2(it2, T[3]));
        mb[0] = make_ulonglong2(mul2(ib2, B[0]), mul2(ib2, B[1]));
        mb[1] = make_ulonglong2(mul2(ib2, B[2]), mul2(ib2, B[3]));
        if (sl == 0) {
            wlog[2 * k]     = 0.5f * logf(fmaxf(dpp, EPSV2));
            wlog[2 * k + 1] = 0.5f * logf(fmaxf(dqq, EPSV2));
        }
    }
    __syncthreads();

    // ---- O = U diag(w) U^T, 4x4 register tile per thread ----
    const int ta = tid >> 4;
    const int tb = tid & 15;
    float acc[4][4];
    #pragma unroll
    for (int i = 0; i < 4; ++i)
        #pragma unroll
        for (int j = 0; j < 4; ++j) acc[i][j] = 0.0f;

    for (int kk = 0; kk < 64; ++kk) {
        float w = wlog[kk];
        float4 ur = *reinterpret_cast<const float4*>(SH + kk * 64 + 4 * ta);
        float4 uc = *reinterpret_cast<const float4*>(SH + kk * 64 + 4 * tb);
        float r0 = w * ur.x, r1 = w * ur.y, r2 = w * ur.z, r3 = w * ur.w;
        acc[0][0] += r0 * uc.x; acc[0][1] += r0 * uc.y; acc[0][2] += r0 * uc.z; acc[0][3] += r0 * uc.w;
        acc[1][0] += r1 * uc.x; acc[1][1] += r1 * uc.y; acc[1][2] += r1 * uc.z; acc[1][3] += r1 * uc.w;
        acc[2][0] += r2 * uc.x; acc[2][1] += r2 * uc.y; acc[2][2] += r2 * uc.z; acc[2][3] += r2 * uc.w;
        acc[3][0] += r3 * uc.x; acc[3][1] += r3 * uc.y; acc[3][2] += r3 * uc.z; acc[3][3] += r3 * uc.w;
    }

    float* go = out + base;
    #pragma unroll
    for (int i = 0; i < 4; ++i) {
        float4 v = make_float4(acc[i][0], acc[i][1], acc[i][2], acc[i][3]);
        *reinterpret_cast<float4*>(go + (4 * ta + i) * 64 + 4 * tb) = v;
    }
#undef VISIT
}

extern "C" void kernel_launch(void* const* d_in, const int* in_sizes, int n_in,
                              void* d_out, int out_size)
{
    const float* x = (const float*)d_in[0];
    float* out = (float*)d_out;
    int batches = in_sizes[0] / 4096;
    logm_jacobi_kernel<<<batches, 256>>>(x, out);
}